// round 3
// baseline (speedup 1.0000x reference)
#include <cuda_runtime.h>
#include <cuda_bf16.h>

// Problem dims (fixed by reference setup_inputs)
#define BATCH   16
#define SEQ     1024
#define DDIM    1024
#define MLPD    500
#define ROWS    (BATCH * SEQ)     // 16384
#define NTOT    (2 * MLPD)        // 1000 (dep cols 0..499, head cols 500..999)
#define NEG_SLOPE 0.01f

// Scratch: per-row scores: slot 0,1 = dep_c0, dep_c1 ; slot 2,3 = head_c0, head_c1
__device__ float g_scores[ROWS * 4];

// ---------------------------------------------------------------------------
// Kernel 0: zero the scratch (graph-replayable, deterministic)
// ---------------------------------------------------------------------------
__global__ void zero_scores_kernel() {
    int idx = blockIdx.x * blockDim.x + threadIdx.x;
    if (idx < ROWS * 4) g_scores[idx] = 0.0f;
}

// ---------------------------------------------------------------------------
// Kernel 1: fused GEMM [16384,1024] x [1024,1000] + bias + leaky + Wc reduce
// Tiling: BM=128, BN=128, BK=16; 256 threads; 8x8 micro-tile per thread.
// Double-buffered SMEM tiles with register-staged prefetch.
// Epilogue: per-thread partials -> 16-lane shuffle reduce -> global atomicAdd.
// ---------------------------------------------------------------------------
#define BM 128
#define BN 128
#define BK 16
#define TM 8
#define TN 8

__global__ __launch_bounds__(256)
void gemm_scores_kernel(const float* __restrict__ A,    // hidden [ROWS, DDIM]
                        const float* __restrict__ Wd,   // [DDIM, MLPD]
                        const float* __restrict__ bd,   // [MLPD]
                        const float* __restrict__ Wh,   // [DDIM, MLPD]
                        const float* __restrict__ bh,   // [MLPD]
                        const float* __restrict__ Wc)   // [NTOT, 2]
{
    __shared__ float As[2][BK][BM];   // transposed A tiles (double buffered)
    __shared__ float Bs[2][BK][BN];

    const int tid = threadIdx.x;
    const int tr  = tid >> 4;      // 0..15  (row group of 8)
    const int tc  = tid & 15;      // 0..15  (col group of 8)

    const int row0 = blockIdx.y * BM;
    const int n0   = blockIdx.x * BN;

    // A-load geometry: 2 float4 per thread
    const int aidx0 = tid * 2;
    const int ar0   = aidx0 >> 2;           // row in tile for first float4
    const int akq0  = aidx0 & 3;
    const int ar1   = (aidx0 + 1) >> 2;
    const int akq1  = (aidx0 + 1) & 3;

    float acc[TM][TN];
    #pragma unroll
    for (int i = 0; i < TM; i++)
        #pragma unroll
        for (int j = 0; j < TN; j++) acc[i][j] = 0.0f;

    // ---- helper lambdas (inlined) ----
    auto load_A_regs = [&](int kt, float4& v0, float4& v1) {
        v0 = *reinterpret_cast<const float4*>(
            &A[(size_t)(row0 + ar0) * DDIM + kt + akq0 * 4]);
        v1 = *reinterpret_cast<const float4*>(
            &A[(size_t)(row0 + ar1) * DDIM + kt + akq1 * 4]);
    };
    auto load_B_regs = [&](int kt, float (&bv)[8]) {
        #pragma unroll
        for (int t = 0; t < 8; t++) {
            int e  = tid + t * 256;       // 0..2047
            int kk = e >> 7;              // 0..15
            int nn = e & 127;             // 0..127
            int n  = n0 + nn;
            float v = 0.0f;
            if (n < MLPD)       v = Wd[(size_t)(kt + kk) * MLPD + n];
            else if (n < NTOT)  v = Wh[(size_t)(kt + kk) * MLPD + (n - MLPD)];
            bv[t] = v;
        }
    };
    auto store_tiles = [&](int buf, const float4& v0, const float4& v1,
                           const float (&bv)[8]) {
        As[buf][akq0 * 4 + 0][ar0] = v0.x;
        As[buf][akq0 * 4 + 1][ar0] = v0.y;
        As[buf][akq0 * 4 + 2][ar0] = v0.z;
        As[buf][akq0 * 4 + 3][ar0] = v0.w;
        As[buf][akq1 * 4 + 0][ar1] = v1.x;
        As[buf][akq1 * 4 + 1][ar1] = v1.y;
        As[buf][akq1 * 4 + 2][ar1] = v1.z;
        As[buf][akq1 * 4 + 3][ar1] = v1.w;
        #pragma unroll
        for (int t = 0; t < 8; t++) {
            int e  = tid + t * 256;
            int kk = e >> 7;
            int nn = e & 127;
            Bs[buf][kk][nn] = bv[t];
        }
    };

    // Prologue: load first tile into buffer 0
    {
        float4 v0, v1; float bv[8];
        load_A_regs(0, v0, v1);
        load_B_regs(0, bv);
        store_tiles(0, v0, v1, bv);
    }
    __syncthreads();

    int buf = 0;
    for (int kt = 0; kt < DDIM; kt += BK) {
        // Prefetch next tile into registers while computing current
        float4 nv0, nv1; float nbv[8];
        const bool has_next = (kt + BK) < DDIM;
        if (has_next) {
            load_A_regs(kt + BK, nv0, nv1);
            load_B_regs(kt + BK, nbv);
        }

        // --- Compute on current buffer ---
        #pragma unroll
        for (int kk = 0; kk < BK; kk++) {
            float ar[TM], br[TN];
            float4 a0 = *reinterpret_cast<const float4*>(&As[buf][kk][tr * TM]);
            float4 a1 = *reinterpret_cast<const float4*>(&As[buf][kk][tr * TM + 4]);
            ar[0]=a0.x; ar[1]=a0.y; ar[2]=a0.z; ar[3]=a0.w;
            ar[4]=a1.x; ar[5]=a1.y; ar[6]=a1.z; ar[7]=a1.w;
            float4 b0 = *reinterpret_cast<const float4*>(&Bs[buf][kk][tc * TN]);
            float4 b1 = *reinterpret_cast<const float4*>(&Bs[buf][kk][tc * TN + 4]);
            br[0]=b0.x; br[1]=b0.y; br[2]=b0.z; br[3]=b0.w;
            br[4]=b1.x; br[5]=b1.y; br[6]=b1.z; br[7]=b1.w;
            #pragma unroll
            for (int i = 0; i < TM; i++)
                #pragma unroll
                for (int j = 0; j < TN; j++)
                    acc[i][j] = fmaf(ar[i], br[j], acc[i][j]);
        }

        if (has_next) {
            store_tiles(buf ^ 1, nv0, nv1, nbv);
            __syncthreads();
            buf ^= 1;
        }
    }

    // --- Epilogue: bias + leaky + Wc contraction into 4 slots per row ---
    float part[TM][4];
    #pragma unroll
    for (int i = 0; i < TM; i++)
        #pragma unroll
        for (int s = 0; s < 4; s++) part[i][s] = 0.0f;

    #pragma unroll
    for (int j = 0; j < TN; j++) {
        int n = n0 + tc * TN + j;
        if (n >= NTOT) continue;
        float bias = (n < MLPD) ? bd[n] : bh[n - MLPD];
        float wc0  = Wc[n * 2 + 0];
        float wc1  = Wc[n * 2 + 1];
        int   s    = (n < MLPD) ? 0 : 2;
        #pragma unroll
        for (int i = 0; i < TM; i++) {
            float v = acc[i][j] + bias;
            v = (v > 0.0f) ? v : NEG_SLOPE * v;
            part[i][s + 0] += v * wc0;
            part[i][s + 1] += v * wc1;
        }
    }

    // Reduce across the 16 tc-lanes sharing the same rows (16-lane segments).
    #pragma unroll
    for (int i = 0; i < TM; i++)
        #pragma unroll
        for (int s = 0; s < 4; s++) {
            float v = part[i][s];
            v += __shfl_down_sync(0xffffffffu, v, 8, 16);
            v += __shfl_down_sync(0xffffffffu, v, 4, 16);
            v += __shfl_down_sync(0xffffffffu, v, 2, 16);
            v += __shfl_down_sync(0xffffffffu, v, 1, 16);
            part[i][s] = v;
        }

    if (tc == 0) {
        #pragma unroll
        for (int i = 0; i < TM; i++) {
            int row = row0 + tr * TM + i;
            #pragma unroll
            for (int s = 0; s < 4; s++)
                atomicAdd(&g_scores[row * 4 + s], part[i][s]);
        }
    }
}

// ---------------------------------------------------------------------------
// Kernel 2: broadcast pairwise add -> out[b,i,j,c] (float4-vectorized writes)
// One block per (b, i) output row of 1024*2 floats.
// ---------------------------------------------------------------------------
__global__ __launch_bounds__(256)
void broadcast_add_kernel(const float* __restrict__ bc, float* __restrict__ out)
{
    __shared__ float hs[SEQ * 2];   // head scores for this batch
    const int row = blockIdx.x;     // b*SEQ + i
    const int b   = row >> 10;
    const int tid = threadIdx.x;

    for (int j = tid; j < SEQ; j += 256) {
        int hr = (b << 10) + j;
        hs[2 * j + 0] = g_scores[hr * 4 + 2];
        hs[2 * j + 1] = g_scores[hr * 4 + 3];
    }
    __syncthreads();

    const float d0 = g_scores[row * 4 + 0] + bc[0];
    const float d1 = g_scores[row * 4 + 1] + bc[1];

    float4* o = reinterpret_cast<float4*>(out + (size_t)row * (SEQ * 2));
    #pragma unroll
    for (int f = tid; f < SEQ * 2 / 4; f += 256) {   // 512 float4 per row
        int j = 2 * f;
        float4 v;
        v.x = d0 + hs[2 * j + 0];
        v.y = d1 + hs[2 * j + 1];
        v.z = d0 + hs[2 * j + 2];
        v.w = d1 + hs[2 * j + 3];
        o[f] = v;
    }
}

// ---------------------------------------------------------------------------
// Launch
// ---------------------------------------------------------------------------
extern "C" void kernel_launch(void* const* d_in, const int* in_sizes, int n_in,
                              void* d_out, int out_size)
{
    (void)in_sizes; (void)n_in; (void)out_size;
    const float* hidden = (const float*)d_in[0];
    const float* Wd     = (const float*)d_in[1];
    const float* bd     = (const float*)d_in[2];
    const float* Wh     = (const float*)d_in[3];
    const float* bh     = (const float*)d_in[4];
    const float* Wc     = (const float*)d_in[5];
    const float* bc     = (const float*)d_in[6];
    float* out          = (float*)d_out;

    zero_scores_kernel<<<(ROWS * 4 + 255) / 256, 256>>>();

    dim3 grid((NTOT + BN - 1) / BN, ROWS / BM);   // (8, 128)
    gemm_scores_kernel<<<grid, 256>>>(hidden, Wd, bd, Wh, bh, Wc);

    broadcast_add_kernel<<<ROWS, 256>>>(bc, out);
}

// round 7
// speedup vs baseline: 2.7092x; 2.7092x over previous
#include <cuda_runtime.h>
#include <cuda_bf16.h>
#include <stdint.h>

// ---------------------------------------------------------------------------
// Problem dims (fixed by reference setup_inputs)
// ---------------------------------------------------------------------------
#define BATCH   16
#define SEQ     1024
#define DDIM    1024
#define MLPD    500
#define ROWS    (BATCH * SEQ)     // 16384
#define NTOT    (2 * MLPD)        // 1000
#define NPAD    1024
#define NEG_SLOPE 0.01f

// ---------------------------------------------------------------------------
// Device scratch (static __device__ arrays: the sanctioned alloc-free path)
// ---------------------------------------------------------------------------
__device__ float          g_scores[ROWS * 4];
__device__ __nv_bfloat16  g_a_hi[ROWS * DDIM];      // 32 MB
__device__ __nv_bfloat16  g_a_lo[ROWS * DDIM];      // 32 MB
__device__ __nv_bfloat16  g_wt_hi[NPAD * DDIM];     // 2 MB  [n][k], rows >=1000 zero
__device__ __nv_bfloat16  g_wt_lo[NPAD * DDIM];     // 2 MB

// ---------------------------------------------------------------------------
// Helpers (sm_100-safe: cp.async / ldmatrix / mma.sync only)
// ---------------------------------------------------------------------------
__device__ __forceinline__ uint32_t smem_u32(const void* p) {
    uint32_t a;
    asm("{ .reg .u64 t; cvta.to.shared.u64 t, %1; cvt.u32.u64 %0, t; }"
        : "=r"(a) : "l"(p));
    return a;
}

#define CP_ASYNC16(dst, src) \
    asm volatile("cp.async.cg.shared.global [%0], [%1], 16;" \
                 :: "r"(dst), "l"(src) : "memory")
#define CP_COMMIT()  asm volatile("cp.async.commit_group;" ::: "memory")
#define CP_WAIT1()   asm volatile("cp.async.wait_group 1;" ::: "memory")

#define LDSM_X4(r0, r1, r2, r3, addr) \
    asm volatile("ldmatrix.sync.aligned.m8n8.x4.shared.b16 {%0,%1,%2,%3}, [%4];" \
                 : "=r"(r0), "=r"(r1), "=r"(r2), "=r"(r3) : "r"(addr))

#define MMA_16816(d, a0, a1, a2, a3, b0, b1) \
    asm volatile("mma.sync.aligned.m16n8k16.row.col.f32.bf16.bf16.f32 " \
                 "{%0,%1,%2,%3}, {%4,%5,%6,%7}, {%8,%9}, {%0,%1,%2,%3};" \
                 : "+f"((d)[0]), "+f"((d)[1]), "+f"((d)[2]), "+f"((d)[3]) \
                 : "r"(a0), "r"(a1), "r"(a2), "r"(a3), "r"(b0), "r"(b1))

// ---------------------------------------------------------------------------
// Kernel 0: zero scores scratch
// ---------------------------------------------------------------------------
__global__ void zero_scores_kernel() {
    int idx = blockIdx.x * blockDim.x + threadIdx.x;
    if (idx < ROWS * 4) g_scores[idx] = 0.0f;
}

// ---------------------------------------------------------------------------
// Kernel 1: split hidden fp32 -> bf16 hi/lo
// ---------------------------------------------------------------------------
__global__ __launch_bounds__(256)
void convert_a_kernel(const float* __restrict__ A) {
    int i = blockIdx.x * blockDim.x + threadIdx.x;        // float4 index
    float4 v = reinterpret_cast<const float4*>(A)[i];
    __nv_bfloat16 h0 = __float2bfloat16(v.x);
    __nv_bfloat16 h1 = __float2bfloat16(v.y);
    __nv_bfloat16 h2 = __float2bfloat16(v.z);
    __nv_bfloat16 h3 = __float2bfloat16(v.w);
    __nv_bfloat16 l0 = __float2bfloat16(v.x - __bfloat162float(h0));
    __nv_bfloat16 l1 = __float2bfloat16(v.y - __bfloat162float(h1));
    __nv_bfloat16 l2 = __float2bfloat16(v.z - __bfloat162float(h2));
    __nv_bfloat16 l3 = __float2bfloat16(v.w - __bfloat162float(h3));
    __nv_bfloat162* H = reinterpret_cast<__nv_bfloat162*>(g_a_hi);
    __nv_bfloat162* L = reinterpret_cast<__nv_bfloat162*>(g_a_lo);
    __nv_bfloat162 p0; p0.x = h0; p0.y = h1;
    __nv_bfloat162 p1; p1.x = h2; p1.y = h3;
    __nv_bfloat162 q0; q0.x = l0; q0.y = l1;
    __nv_bfloat162 q1; q1.x = l2; q1.y = l3;
    H[2 * i + 0] = p0;  H[2 * i + 1] = p1;
    L[2 * i + 0] = q0;  L[2 * i + 1] = q1;
}

// ---------------------------------------------------------------------------
// Kernel 2: transpose + split W_dep|W_head fp32 -> bf16 [NPAD][DDIM] hi/lo
// ---------------------------------------------------------------------------
__global__ __launch_bounds__(256)
void transpose_w_kernel(const float* __restrict__ Wd, const float* __restrict__ Wh) {
    __shared__ float tile[32][33];
    const int n0 = blockIdx.x * 32;
    const int k0 = blockIdx.y * 32;
    const int tx = threadIdx.x, ty = threadIdx.y;    // 32 x 8

    #pragma unroll
    for (int i = 0; i < 4; i++) {
        int k = k0 + ty + i * 8;
        int n = n0 + tx;
        float val = 0.0f;
        if (n < MLPD)       val = Wd[(size_t)k * MLPD + n];
        else if (n < NTOT)  val = Wh[(size_t)k * MLPD + (n - MLPD)];
        tile[ty + i * 8][tx] = val;              // tile[kk][nn]
    }
    __syncthreads();
    #pragma unroll
    for (int i = 0; i < 4; i++) {
        int n = n0 + ty + i * 8;
        int k = k0 + tx;
        float x = tile[tx][ty + i * 8];
        __nv_bfloat16 h = __float2bfloat16(x);
        __nv_bfloat16 l = __float2bfloat16(x - __bfloat162float(h));
        g_wt_hi[(size_t)n * DDIM + k] = h;
        g_wt_lo[(size_t)n * DDIM + k] = l;
    }
}

// ---------------------------------------------------------------------------
// Kernel 3: bf16-split mma.sync GEMM + fused epilogue
// Grid (8, 128), 256 threads (8 warps: 2 m x 4 n), 128x128x32 CTA tile.
// 3-stage cp.async pipeline. 3 MMA passes: hi*hi + lo*hi + hi*lo.
// ---------------------------------------------------------------------------
#define BM 128
#define BN 128
#define BK 32
#define STAGES 3
#define MAT_BYTES  (BM * BK * 2)      // 8192
#define STAGE_B    (4 * MAT_BYTES)    // 32768
#define AHI 0
#define ALO MAT_BYTES
#define BHI (2 * MAT_BYTES)
#define BLO (3 * MAT_BYTES)
#define DYN_SMEM   (STAGES * STAGE_B) // 98304

__global__ __launch_bounds__(256)
void gemm_mma_kernel(const float* __restrict__ bdep, const float* __restrict__ bhead,
                     const float* __restrict__ Wc) {
    extern __shared__ char smem[];
    const uint32_t sb = smem_u32(smem);

    const int tid    = threadIdx.x;
    const int lane   = tid & 31;
    const int wid    = tid >> 5;
    const int warp_m = wid & 1;        // 0..1
    const int warp_n = wid >> 1;       // 0..3
    const int row0   = blockIdx.y * BM;
    const int n0     = blockIdx.x * BN;

    // per-lane ldmatrix geometry
    const int a_mlane = (lane & 15);          // row within 16-row A tile
    const int a_kh    = lane >> 4;            // k-half (0/1)
    const int b_nlane = (lane & 7) + ((lane >> 4) << 3);  // row within 16-row B pair
    const int b_kh    = (lane >> 3) & 1;

    float acc[4][4][4];
    #pragma unroll
    for (int i = 0; i < 4; i++)
        #pragma unroll
        for (int j = 0; j < 4; j++)
            #pragma unroll
            for (int e = 0; e < 4; e++) acc[i][j][e] = 0.0f;

    // ---- stage loader: 2 chunks per matrix per thread, 16B cp.async ----
    auto load_stage = [&](int stage, int kt) {
        const uint32_t s0 = sb + stage * STAGE_B;
        #pragma unroll
        for (int i = 0; i < 2; i++) {
            int idx = tid + i * 256;          // 0..511
            int m  = idx >> 2;                // row 0..127
            int kc = idx & 3;                 // 16B chunk 0..3
            uint32_t doff = (uint32_t)(m * 64 + ((kc ^ (m & 3)) << 4));
            size_t gsrc = (size_t)(row0 + m) * DDIM + kt + kc * 8;
            size_t gsrcB = (size_t)(n0 + m) * DDIM + kt + kc * 8;
            CP_ASYNC16(s0 + AHI + doff, (const void*)(g_a_hi + gsrc));
            CP_ASYNC16(s0 + ALO + doff, (const void*)(g_a_lo + gsrc));
            CP_ASYNC16(s0 + BHI + doff, (const void*)(g_wt_hi + gsrcB));
            CP_ASYNC16(s0 + BLO + doff, (const void*)(g_wt_lo + gsrcB));
        }
    };

    // prologue: stages 0 and 1
    load_stage(0, 0);
    CP_COMMIT();
    load_stage(1, BK);
    CP_COMMIT();

    const int NKC = DDIM / BK;   // 32
    for (int kc = 0; kc < NKC; kc++) {
        CP_WAIT1();
        __syncthreads();

        // issue loads for kc+2 into the stage freed last iteration
        if (kc + 2 < NKC) load_stage((kc + 2) % STAGES, (kc + 2) * BK);
        CP_COMMIT();

        const uint32_t s0 = sb + (kc % STAGES) * STAGE_B;

        #pragma unroll
        for (int ks = 0; ks < 2; ks++) {
            uint32_t ah[4][4], al[4][4], bh[8], bl[8];
            // A fragments (4 m-tiles)
            #pragma unroll
            for (int mt = 0; mt < 4; mt++) {
                int m = warp_m * 64 + mt * 16 + a_mlane;
                uint32_t off = (uint32_t)(m * 64 + (((ks * 2 + a_kh) ^ (m & 3)) << 4));
                LDSM_X4(ah[mt][0], ah[mt][1], ah[mt][2], ah[mt][3], s0 + AHI + off);
                LDSM_X4(al[mt][0], al[mt][1], al[mt][2], al[mt][3], s0 + ALO + off);
            }
            // B fragments (2 n-tile pairs -> 4 n-tiles)
            #pragma unroll
            for (int np = 0; np < 2; np++) {
                int n = warp_n * 32 + np * 16 + b_nlane;
                uint32_t off = (uint32_t)(n * 64 + (((ks * 2 + b_kh) ^ (n & 3)) << 4));
                LDSM_X4(bh[np * 4 + 0], bh[np * 4 + 1], bh[np * 4 + 2], bh[np * 4 + 3],
                        s0 + BHI + off);
                LDSM_X4(bl[np * 4 + 0], bl[np * 4 + 1], bl[np * 4 + 2], bl[np * 4 + 3],
                        s0 + BLO + off);
            }
            // 3 passes: hi*hi, lo*hi, hi*lo
            #pragma unroll
            for (int mt = 0; mt < 4; mt++) {
                #pragma unroll
                for (int nt = 0; nt < 4; nt++) {
                    int bi = (nt >> 1) * 4 + (nt & 1) * 2;
                    MMA_16816(acc[mt][nt], ah[mt][0], ah[mt][1], ah[mt][2], ah[mt][3],
                              bh[bi], bh[bi + 1]);
                    MMA_16816(acc[mt][nt], al[mt][0], al[mt][1], al[mt][2], al[mt][3],
                              bh[bi], bh[bi + 1]);
                    MMA_16816(acc[mt][nt], ah[mt][0], ah[mt][1], ah[mt][2], ah[mt][3],
                              bl[bi], bl[bi + 1]);
                }
            }
        }
    }

    // ---- epilogue: bias + leaky + Wc contraction, quad reduce, atomicAdd ----
    float part[4][2][4];
    #pragma unroll
    for (int mt = 0; mt < 4; mt++)
        #pragma unroll
        for (int h = 0; h < 2; h++)
            #pragma unroll
            for (int s = 0; s < 4; s++) part[mt][h][s] = 0.0f;

    #pragma unroll
    for (int nt = 0; nt < 4; nt++) {
        #pragma unroll
        for (int e = 0; e < 4; e++) {
            int n = n0 + warp_n * 32 + nt * 8 + (lane & 3) * 2 + (e & 1);
            if (n >= NTOT) continue;
            float bias = (n < MLPD) ? __ldg(bdep + n) : __ldg(bhead + n - MLPD);
            float w0 = __ldg(Wc + 2 * n);
            float w1 = __ldg(Wc + 2 * n + 1);
            int s = (n < MLPD) ? 0 : 2;
            int half = e >> 1;
            #pragma unroll
            for (int mt = 0; mt < 4; mt++) {
                float v = acc[mt][nt][e] + bias;
                v = (v > 0.0f) ? v : NEG_SLOPE * v;
                part[mt][half][s + 0] += v * w0;
                part[mt][half][s + 1] += v * w1;
            }
        }
    }

    // reduce across the 4 lanes of each quad (they share the same rows)
    #pragma unroll
    for (int mt = 0; mt < 4; mt++)
        #pragma unroll
        for (int h = 0; h < 2; h++)
            #pragma unroll
            for (int s = 0; s < 4; s++) {
                float v = part[mt][h][s];
                v += __shfl_xor_sync(0xffffffffu, v, 1);
                v += __shfl_xor_sync(0xffffffffu, v, 2);
                part[mt][h][s] = v;
            }

    if ((lane & 3) == 0) {
        #pragma unroll
        for (int mt = 0; mt < 4; mt++)
            #pragma unroll
            for (int h = 0; h < 2; h++) {
                int row = row0 + warp_m * 64 + mt * 16 + (lane >> 2) + h * 8;
                #pragma unroll
                for (int s = 0; s < 4; s++)
                    atomicAdd(&g_scores[row * 4 + s], part[mt][h][s]);
            }
    }
}

// ---------------------------------------------------------------------------
// Kernel 4: broadcast pairwise add -> out[b,i,j,c]
// ---------------------------------------------------------------------------
__global__ __launch_bounds__(256)
void broadcast_add_kernel(const float* __restrict__ bc, float* __restrict__ out) {
    __shared__ float hs[SEQ * 2];
    const int row = blockIdx.x;
    const int b   = row >> 10;
    const int tid = threadIdx.x;

    for (int j = tid; j < SEQ; j += 256) {
        int hr = (b << 10) + j;
        hs[2 * j + 0] = g_scores[hr * 4 + 2];
        hs[2 * j + 1] = g_scores[hr * 4 + 3];
    }
    __syncthreads();

    const float d0 = g_scores[row * 4 + 0] + bc[0];
    const float d1 = g_scores[row * 4 + 1] + bc[1];

    float4* o = reinterpret_cast<float4*>(out + (size_t)row * (SEQ * 2));
    for (int f = tid; f < SEQ * 2 / 4; f += 256) {
        int j = 2 * f;
        float4 v;
        v.x = d0 + hs[2 * j + 0];
        v.y = d1 + hs[2 * j + 1];
        v.z = d0 + hs[2 * j + 2];
        v.w = d1 + hs[2 * j + 3];
        o[f] = v;
    }
}

// ---------------------------------------------------------------------------
// Launch
// ---------------------------------------------------------------------------
extern "C" void kernel_launch(void* const* d_in, const int* in_sizes, int n_in,
                              void* d_out, int out_size)
{
    (void)in_sizes; (void)n_in; (void)out_size;
    const float* hidden = (const float*)d_in[0];
    const float* Wd     = (const float*)d_in[1];
    const float* bd     = (const float*)d_in[2];
    const float* Wh     = (const float*)d_in[3];
    const float* bh     = (const float*)d_in[4];
    const float* Wc     = (const float*)d_in[5];
    const float* bc     = (const float*)d_in[6];
    float* out          = (float*)d_out;

    cudaFuncSetAttribute(gemm_mma_kernel,
                         cudaFuncAttributeMaxDynamicSharedMemorySize, DYN_SMEM);

    zero_scores_kernel<<<(ROWS * 4 + 255) / 256, 256>>>();
    convert_a_kernel<<<ROWS * DDIM / 4 / 256, 256>>>(hidden);
    transpose_w_kernel<<<dim3(NPAD / 32, DDIM / 32), dim3(32, 8)>>>(Wd, Wh);
    gemm_mma_kernel<<<dim3(NPAD / BN, ROWS / BM), 256, DYN_SMEM>>>(bd, bh, Wc);
    broadcast_add_kernel<<<ROWS, 256>>>(bc, out);
}

// round 9
// speedup vs baseline: 3.2933x; 1.2156x over previous
#include <cuda_runtime.h>
#include <cuda_fp16.h>
#include <stdint.h>

// ---------------------------------------------------------------------------
// Problem dims (fixed by reference setup_inputs)
// ---------------------------------------------------------------------------
#define BATCH   16
#define SEQ     1024
#define DDIM    1024
#define MLPD    500
#define ROWS    (BATCH * SEQ)     // 16384
#define NTOT    (2 * MLPD)        // 1000
#define NPAD    1024
#define NEG_SLOPE 0.01f

// ---------------------------------------------------------------------------
// Device scratch (static __device__ arrays: the sanctioned alloc-free path)
// A is split fp16 hi+lo (captures ~21 mantissa bits); B is single fp16.
// Dominant error = B quantization 2^-11, averaged over K=1024 -> ~3e-4 norm.
// ---------------------------------------------------------------------------
__device__ float   g_scores[ROWS * 4];
__device__ __half  g_a_hi[ROWS * DDIM];      // 32 MB
__device__ __half  g_a_lo[ROWS * DDIM];      // 32 MB
__device__ __half  g_wt[NPAD * DDIM];        // 2 MB  [n][k], rows >=1000 zero

// ---------------------------------------------------------------------------
// Helpers (sm_100-safe: cp.async / ldmatrix / mma.sync only)
// ---------------------------------------------------------------------------
__device__ __forceinline__ uint32_t smem_u32(const void* p) {
    uint32_t a;
    asm("{ .reg .u64 t; cvta.to.shared.u64 t, %1; cvt.u32.u64 %0, t; }"
        : "=r"(a) : "l"(p));
    return a;
}

#define CP_ASYNC16(dst, src) \
    asm volatile("cp.async.cg.shared.global [%0], [%1], 16;" \
                 :: "r"(dst), "l"(src) : "memory")
#define CP_COMMIT()  asm volatile("cp.async.commit_group;" ::: "memory")
#define CP_WAIT1()   asm volatile("cp.async.wait_group 1;" ::: "memory")

#define LDSM_X4(r0, r1, r2, r3, addr) \
    asm volatile("ldmatrix.sync.aligned.m8n8.x4.shared.b16 {%0,%1,%2,%3}, [%4];" \
                 : "=r"(r0), "=r"(r1), "=r"(r2), "=r"(r3) : "r"(addr))

#define MMA_16816(d, a0, a1, a2, a3, b0, b1) \
    asm volatile("mma.sync.aligned.m16n8k16.row.col.f32.f16.f16.f32 " \
                 "{%0,%1,%2,%3}, {%4,%5,%6,%7}, {%8,%9}, {%0,%1,%2,%3};" \
                 : "+f"((d)[0]), "+f"((d)[1]), "+f"((d)[2]), "+f"((d)[3]) \
                 : "r"(a0), "r"(a1), "r"(a2), "r"(a3), "r"(b0), "r"(b1))

// ---------------------------------------------------------------------------
// Kernel 0: zero scores scratch
// ---------------------------------------------------------------------------
__global__ void zero_scores_kernel() {
    int idx = blockIdx.x * blockDim.x + threadIdx.x;
    if (idx < ROWS * 4) g_scores[idx] = 0.0f;
}

// ---------------------------------------------------------------------------
// Kernel 1: split hidden fp32 -> fp16 hi/lo
// ---------------------------------------------------------------------------
__global__ __launch_bounds__(256)
void convert_a_kernel(const float* __restrict__ A) {
    int i = blockIdx.x * blockDim.x + threadIdx.x;        // float4 index
    float4 v = reinterpret_cast<const float4*>(A)[i];
    __half h0 = __float2half(v.x);
    __half h1 = __float2half(v.y);
    __half h2 = __float2half(v.z);
    __half h3 = __float2half(v.w);
    __half l0 = __float2half(v.x - __half2float(h0));
    __half l1 = __float2half(v.y - __half2float(h1));
    __half l2 = __float2half(v.z - __half2float(h2));
    __half l3 = __float2half(v.w - __half2float(h3));
    __half2* H = reinterpret_cast<__half2*>(g_a_hi);
    __half2* L = reinterpret_cast<__half2*>(g_a_lo);
    __half2 p0; p0.x = h0; p0.y = h1;
    __half2 p1; p1.x = h2; p1.y = h3;
    __half2 q0; q0.x = l0; q0.y = l1;
    __half2 q1; q1.x = l2; q1.y = l3;
    H[2 * i + 0] = p0;  H[2 * i + 1] = p1;
    L[2 * i + 0] = q0;  L[2 * i + 1] = q1;
}

// ---------------------------------------------------------------------------
// Kernel 2: transpose W_dep|W_head fp32 -> fp16 [NPAD][DDIM]
// ---------------------------------------------------------------------------
__global__ __launch_bounds__(256)
void transpose_w_kernel(const float* __restrict__ Wd, const float* __restrict__ Wh) {
    __shared__ float tile[32][33];
    const int n0 = blockIdx.x * 32;
    const int k0 = blockIdx.y * 32;
    const int tx = threadIdx.x, ty = threadIdx.y;    // 32 x 8

    #pragma unroll
    for (int i = 0; i < 4; i++) {
        int k = k0 + ty + i * 8;
        int n = n0 + tx;
        float val = 0.0f;
        if (n < MLPD)       val = Wd[(size_t)k * MLPD + n];
        else if (n < NTOT)  val = Wh[(size_t)k * MLPD + (n - MLPD)];
        tile[ty + i * 8][tx] = val;              // tile[kk][nn]
    }
    __syncthreads();
    #pragma unroll
    for (int i = 0; i < 4; i++) {
        int n = n0 + ty + i * 8;
        int k = k0 + tx;
        g_wt[(size_t)n * DDIM + k] = __float2half(tile[tx][ty + i * 8]);
    }
}

// ---------------------------------------------------------------------------
// Kernel 3: fp16-split mma.sync GEMM + fused epilogue
// Grid (8, 128), 256 threads (8 warps: 2 m x 4 n), 128x128x32 CTA tile.
// 3-stage cp.async pipeline. 2 MMA passes: a_hi*b + a_lo*b.
// ---------------------------------------------------------------------------
#define BM 128
#define BN 128
#define BK 32
#define STAGES 3
#define MAT_BYTES  (BM * BK * 2)      // 8192
#define STAGE_B    (3 * MAT_BYTES)    // 24576
#define AHI 0
#define ALO MAT_BYTES
#define BOF (2 * MAT_BYTES)
#define DYN_SMEM   (STAGES * STAGE_B) // 73728

__global__ __launch_bounds__(256)
void gemm_mma_kernel(const float* __restrict__ bdep, const float* __restrict__ bhead,
                     const float* __restrict__ Wc) {
    extern __shared__ char smem[];
    const uint32_t sb = smem_u32(smem);

    const int tid    = threadIdx.x;
    const int lane   = tid & 31;
    const int wid    = tid >> 5;
    const int warp_m = wid & 1;        // 0..1
    const int warp_n = wid >> 1;       // 0..3
    const int row0   = blockIdx.y * BM;
    const int n0     = blockIdx.x * BN;

    // per-lane ldmatrix geometry
    const int a_mlane = (lane & 15);          // row within 16-row A tile
    const int a_kh    = lane >> 4;            // k-half (0/1)
    const int b_nlane = (lane & 7) + ((lane >> 4) << 3);  // row within 16-row B pair
    const int b_kh    = (lane >> 3) & 1;

    float acc[4][4][4];
    #pragma unroll
    for (int i = 0; i < 4; i++)
        #pragma unroll
        for (int j = 0; j < 4; j++)
            #pragma unroll
            for (int e = 0; e < 4; e++) acc[i][j][e] = 0.0f;

    // ---- stage loader: 2 chunks per matrix per thread, 16B cp.async ----
    auto load_stage = [&](int stage, int kt) {
        const uint32_t s0 = sb + stage * STAGE_B;
        #pragma unroll
        for (int i = 0; i < 2; i++) {
            int idx = tid + i * 256;          // 0..511
            int m  = idx >> 2;                // row 0..127
            int kc = idx & 3;                 // 16B chunk 0..3
            uint32_t doff = (uint32_t)(m * 64 + ((kc ^ (m & 3)) << 4));
            size_t gsrc  = (size_t)(row0 + m) * DDIM + kt + kc * 8;
            size_t gsrcB = (size_t)(n0 + m) * DDIM + kt + kc * 8;
            CP_ASYNC16(s0 + AHI + doff, (const void*)(g_a_hi + gsrc));
            CP_ASYNC16(s0 + ALO + doff, (const void*)(g_a_lo + gsrc));
            CP_ASYNC16(s0 + BOF + doff, (const void*)(g_wt + gsrcB));
        }
    };

    // prologue: stages 0 and 1
    load_stage(0, 0);
    CP_COMMIT();
    load_stage(1, BK);
    CP_COMMIT();

    const int NKC = DDIM / BK;   // 32
    for (int kc = 0; kc < NKC; kc++) {
        CP_WAIT1();
        __syncthreads();

        // issue loads for kc+2 into the stage freed last iteration
        if (kc + 2 < NKC) load_stage((kc + 2) % STAGES, (kc + 2) * BK);
        CP_COMMIT();

        const uint32_t s0 = sb + (kc % STAGES) * STAGE_B;

        #pragma unroll
        for (int ks = 0; ks < 2; ks++) {
            uint32_t ah[4][4], al[4][4], bh[8];
            // A fragments (4 m-tiles), hi and lo
            #pragma unroll
            for (int mt = 0; mt < 4; mt++) {
                int m = warp_m * 64 + mt * 16 + a_mlane;
                uint32_t off = (uint32_t)(m * 64 + (((ks * 2 + a_kh) ^ (m & 3)) << 4));
                LDSM_X4(ah[mt][0], ah[mt][1], ah[mt][2], ah[mt][3], s0 + AHI + off);
                LDSM_X4(al[mt][0], al[mt][1], al[mt][2], al[mt][3], s0 + ALO + off);
            }
            // B fragments (2 n-tile pairs -> 4 n-tiles)
            #pragma unroll
            for (int np = 0; np < 2; np++) {
                int n = warp_n * 32 + np * 16 + b_nlane;
                uint32_t off = (uint32_t)(n * 64 + (((ks * 2 + b_kh) ^ (n & 3)) << 4));
                LDSM_X4(bh[np * 4 + 0], bh[np * 4 + 1], bh[np * 4 + 2], bh[np * 4 + 3],
                        s0 + BOF + off);
            }
            // 2 passes: a_hi*b + a_lo*b
            #pragma unroll
            for (int mt = 0; mt < 4; mt++) {
                #pragma unroll
                for (int nt = 0; nt < 4; nt++) {
                    int bi = (nt >> 1) * 4 + (nt & 1) * 2;
                    MMA_16816(acc[mt][nt], ah[mt][0], ah[mt][1], ah[mt][2], ah[mt][3],
                              bh[bi], bh[bi + 1]);
                    MMA_16816(acc[mt][nt], al[mt][0], al[mt][1], al[mt][2], al[mt][3],
                              bh[bi], bh[bi + 1]);
                }
            }
        }
    }

    // ---- epilogue: bias + leaky + Wc contraction, quad reduce, atomicAdd ----
    float part[4][2][4];
    #pragma unroll
    for (int mt = 0; mt < 4; mt++)
        #pragma unroll
        for (int h = 0; h < 2; h++)
            #pragma unroll
            for (int s = 0; s < 4; s++) part[mt][h][s] = 0.0f;

    #pragma unroll
    for (int nt = 0; nt < 4; nt++) {
        #pragma unroll
        for (int e = 0; e < 4; e++) {
            int n = n0 + warp_n * 32 + nt * 8 + (lane & 3) * 2 + (e & 1);
            if (n >= NTOT) continue;
            float bias = (n < MLPD) ? __ldg(bdep + n) : __ldg(bhead + n - MLPD);
            float w0 = __ldg(Wc + 2 * n);
            float w1 = __ldg(Wc + 2 * n + 1);
            int s = (n < MLPD) ? 0 : 2;
            int half = e >> 1;
            #pragma unroll
            for (int mt = 0; mt < 4; mt++) {
                float v = acc[mt][nt][e] + bias;
                v = (v > 0.0f) ? v : NEG_SLOPE * v;
                part[mt][half][s + 0] += v * w0;
                part[mt][half][s + 1] += v * w1;
            }
        }
    }

    // reduce across the 4 lanes of each quad (they share the same rows)
    #pragma unroll
    for (int mt = 0; mt < 4; mt++)
        #pragma unroll
        for (int h = 0; h < 2; h++)
            #pragma unroll
            for (int s = 0; s < 4; s++) {
                float v = part[mt][h][s];
                v += __shfl_xor_sync(0xffffffffu, v, 1);
                v += __shfl_xor_sync(0xffffffffu, v, 2);
                part[mt][h][s] = v;
            }

    if ((lane & 3) == 0) {
        #pragma unroll
        for (int mt = 0; mt < 4; mt++)
            #pragma unroll
            for (int h = 0; h < 2; h++) {
                int row = row0 + warp_m * 64 + mt * 16 + (lane >> 2) + h * 8;
                #pragma unroll
                for (int s = 0; s < 4; s++)
                    atomicAdd(&g_scores[row * 4 + s], part[mt][h][s]);
            }
    }
}

// ---------------------------------------------------------------------------
// Kernel 4: broadcast pairwise add -> out[b,i,j,c]
// ---------------------------------------------------------------------------
__global__ __launch_bounds__(256)
void broadcast_add_kernel(const float* __restrict__ bc, float* __restrict__ out) {
    __shared__ float hs[SEQ * 2];
    const int row = blockIdx.x;
    const int b   = row >> 10;
    const int tid = threadIdx.x;

    for (int j = tid; j < SEQ; j += 256) {
        int hr = (b << 10) + j;
        hs[2 * j + 0] = g_scores[hr * 4 + 2];
        hs[2 * j + 1] = g_scores[hr * 4 + 3];
    }
    __syncthreads();

    const float d0 = g_scores[row * 4 + 0] + bc[0];
    const float d1 = g_scores[row * 4 + 1] + bc[1];

    float4* o = reinterpret_cast<float4*>(out + (size_t)row * (SEQ * 2));
    for (int f = tid; f < SEQ * 2 / 4; f += 256) {
        int j = 2 * f;
        float4 v;
        v.x = d0 + hs[2 * j + 0];
        v.y = d1 + hs[2 * j + 1];
        v.z = d0 + hs[2 * j + 2];
        v.w = d1 + hs[2 * j + 3];
        o[f] = v;
    }
}

// ---------------------------------------------------------------------------
// Launch
// ---------------------------------------------------------------------------
extern "C" void kernel_launch(void* const* d_in, const int* in_sizes, int n_in,
                              void* d_out, int out_size)
{
    (void)in_sizes; (void)n_in; (void)out_size;
    const float* hidden = (const float*)d_in[0];
    const float* Wd     = (const float*)d_in[1];
    const float* bd     = (const float*)d_in[2];
    const float* Wh     = (const float*)d_in[3];
    const float* bh     = (const float*)d_in[4];
    const float* Wc     = (const float*)d_in[5];
    const float* bc     = (const float*)d_in[6];
    float* out          = (float*)d_out;

    cudaFuncSetAttribute(gemm_mma_kernel,
                         cudaFuncAttributeMaxDynamicSharedMemorySize, DYN_SMEM);

    zero_scores_kernel<<<(ROWS * 4 + 255) / 256, 256>>>();
    convert_a_kernel<<<ROWS * DDIM / 4 / 256, 256>>>(hidden);
    transpose_w_kernel<<<dim3(NPAD / 32, DDIM / 32), dim3(32, 8)>>>(Wd, Wh);
    gemm_mma_kernel<<<dim3(NPAD / BN, ROWS / BM), 256, DYN_SMEM>>>(bd, bh, Wc);
    broadcast_add_kernel<<<ROWS, 256>>>(bc, out);
}

// round 11
// speedup vs baseline: 3.6663x; 1.1133x over previous
#include <cuda_runtime.h>
#include <cuda_fp16.h>
#include <stdint.h>

// ---------------------------------------------------------------------------
// Problem dims (fixed by reference setup_inputs)
// ---------------------------------------------------------------------------
#define BATCH   16
#define SEQ     1024
#define DDIM    1024
#define MLPD    500
#define ROWS    (BATCH * SEQ)     // 16384
#define NTOT    (2 * MLPD)        // 1000
#define NPAD    1024
#define NEG_SLOPE 0.01f

// ---------------------------------------------------------------------------
// Device scratch (static __device__ arrays: the sanctioned alloc-free path)
// A is split fp16 hi+lo (captures ~21 mantissa bits); B is single fp16.
// Dominant error = B quantization 2^-11, averaged over K=1024 -> ~3e-4 norm.
// ---------------------------------------------------------------------------
__device__ float   g_scores[ROWS * 4];
__device__ __half  g_a_hi[ROWS * DDIM];      // 32 MB
__device__ __half  g_a_lo[ROWS * DDIM];      // 32 MB
__device__ __half  g_wt[NPAD * DDIM];        // 2 MB  [n][k], rows >=1000 zero

// ---------------------------------------------------------------------------
// Helpers (sm_100-safe: cp.async / ldmatrix / mma.sync only)
// ---------------------------------------------------------------------------
__device__ __forceinline__ uint32_t smem_u32(const void* p) {
    uint32_t a;
    asm("{ .reg .u64 t; cvta.to.shared.u64 t, %1; cvt.u32.u64 %0, t; }"
        : "=r"(a) : "l"(p));
    return a;
}

#define CP_ASYNC16(dst, src) \
    asm volatile("cp.async.cg.shared.global [%0], [%1], 16;" \
                 :: "r"(dst), "l"(src) : "memory")
#define CP_COMMIT()  asm volatile("cp.async.commit_group;" ::: "memory")
#define CP_WAIT1()   asm volatile("cp.async.wait_group 1;" ::: "memory")

#define LDSM_X4(r0, r1, r2, r3, addr) \
    asm volatile("ldmatrix.sync.aligned.m8n8.x4.shared.b16 {%0,%1,%2,%3}, [%4];" \
                 : "=r"(r0), "=r"(r1), "=r"(r2), "=r"(r3) : "r"(addr))

#define MMA_16816(d, a0, a1, a2, a3, b0, b1) \
    asm volatile("mma.sync.aligned.m16n8k16.row.col.f32.f16.f16.f32 " \
                 "{%0,%1,%2,%3}, {%4,%5,%6,%7}, {%8,%9}, {%0,%1,%2,%3};" \
                 : "+f"((d)[0]), "+f"((d)[1]), "+f"((d)[2]), "+f"((d)[3]) \
                 : "r"(a0), "r"(a1), "r"(a2), "r"(a3), "r"(b0), "r"(b1))

// ---------------------------------------------------------------------------
// Kernel 0: zero scores scratch
// ---------------------------------------------------------------------------
__global__ void zero_scores_kernel() {
    int idx = blockIdx.x * blockDim.x + threadIdx.x;
    if (idx < ROWS * 4) g_scores[idx] = 0.0f;
}

// ---------------------------------------------------------------------------
// Kernel 1: split hidden fp32 -> fp16 hi/lo
// ---------------------------------------------------------------------------
__global__ __launch_bounds__(256)
void convert_a_kernel(const float* __restrict__ A) {
    int i = blockIdx.x * blockDim.x + threadIdx.x;        // float4 index
    float4 v = reinterpret_cast<const float4*>(A)[i];
    __half h0 = __float2half(v.x);
    __half h1 = __float2half(v.y);
    __half h2 = __float2half(v.z);
    __half h3 = __float2half(v.w);
    __half l0 = __float2half(v.x - __half2float(h0));
    __half l1 = __float2half(v.y - __half2float(h1));
    __half l2 = __float2half(v.z - __half2float(h2));
    __half l3 = __float2half(v.w - __half2float(h3));
    __half2* H = reinterpret_cast<__half2*>(g_a_hi);
    __half2* L = reinterpret_cast<__half2*>(g_a_lo);
    __half2 p0; p0.x = h0; p0.y = h1;
    __half2 p1; p1.x = h2; p1.y = h3;
    __half2 q0; q0.x = l0; q0.y = l1;
    __half2 q1; q1.x = l2; q1.y = l3;
    H[2 * i + 0] = p0;  H[2 * i + 1] = p1;
    L[2 * i + 0] = q0;  L[2 * i + 1] = q1;
}

// ---------------------------------------------------------------------------
// Kernel 2: transpose W_dep|W_head fp32 -> fp16 [NPAD][DDIM]
// ---------------------------------------------------------------------------
__global__ __launch_bounds__(256)
void transpose_w_kernel(const float* __restrict__ Wd, const float* __restrict__ Wh) {
    __shared__ float tile[32][33];
    const int n0 = blockIdx.x * 32;
    const int k0 = blockIdx.y * 32;
    const int tx = threadIdx.x, ty = threadIdx.y;    // 32 x 8

    #pragma unroll
    for (int i = 0; i < 4; i++) {
        int k = k0 + ty + i * 8;
        int n = n0 + tx;
        float val = 0.0f;
        if (n < MLPD)       val = Wd[(size_t)k * MLPD + n];
        else if (n < NTOT)  val = Wh[(size_t)k * MLPD + (n - MLPD)];
        tile[ty + i * 8][tx] = val;              // tile[kk][nn]
    }
    __syncthreads();
    #pragma unroll
    for (int i = 0; i < 4; i++) {
        int n = n0 + ty + i * 8;
        int k = k0 + tx;
        g_wt[(size_t)n * DDIM + k] = __float2half(tile[tx][ty + i * 8]);
    }
}

// ---------------------------------------------------------------------------
// Kernel 3: fp16-split mma.sync GEMM + fused epilogue
// Grid (8, 128), 256 threads (8 warps: 4 m x 2 n), 128x128x32 CTA tile.
// Warp tile 32x64 (optimal LDSM reuse: A*2 + B*4 = 32KB/ks vs 40KB for 2x4).
// 3-stage cp.async pipeline. 2 MMA passes: a_hi*b + a_lo*b.
// ---------------------------------------------------------------------------
#define BM 128
#define BN 128
#define BK 32
#define STAGES 3
#define MAT_BYTES  (BM * BK * 2)      // 8192
#define STAGE_B    (3 * MAT_BYTES)    // 24576
#define AHI 0
#define ALO MAT_BYTES
#define BOF (2 * MAT_BYTES)
#define DYN_SMEM   (STAGES * STAGE_B) // 73728

__global__ __launch_bounds__(256)
void gemm_mma_kernel(const float* __restrict__ bdep, const float* __restrict__ bhead,
                     const float* __restrict__ Wc) {
    extern __shared__ char smem[];
    const uint32_t sb = smem_u32(smem);

    const int tid    = threadIdx.x;
    const int lane   = tid & 31;
    const int wid    = tid >> 5;
    const int warp_m = wid & 3;        // 0..3  (32-row group)
    const int warp_n = wid >> 2;       // 0..1  (64-col group)
    const int row0   = blockIdx.y * BM;
    const int n0     = blockIdx.x * BN;

    // per-lane ldmatrix geometry
    const int a_mlane = (lane & 15);          // row within 16-row A tile
    const int a_kh    = lane >> 4;            // k-half (0/1)
    const int b_nlane = (lane & 7) + ((lane >> 4) << 3);  // row within 16-row B pair
    const int b_kh    = (lane >> 3) & 1;

    float acc[2][8][4];
    #pragma unroll
    for (int i = 0; i < 2; i++)
        #pragma unroll
        for (int j = 0; j < 8; j++)
            #pragma unroll
            for (int e = 0; e < 4; e++) acc[i][j][e] = 0.0f;

    // ---- stage loader: 2 chunks per matrix per thread, 16B cp.async ----
    auto load_stage = [&](int stage, int kt) {
        const uint32_t s0 = sb + stage * STAGE_B;
        #pragma unroll
        for (int i = 0; i < 2; i++) {
            int idx = tid + i * 256;          // 0..511
            int m  = idx >> 2;                // row 0..127
            int kc = idx & 3;                 // 16B chunk 0..3
            uint32_t doff = (uint32_t)(m * 64 + ((kc ^ (m & 3)) << 4));
            size_t gsrc  = (size_t)(row0 + m) * DDIM + kt + kc * 8;
            size_t gsrcB = (size_t)(n0 + m) * DDIM + kt + kc * 8;
            CP_ASYNC16(s0 + AHI + doff, (const void*)(g_a_hi + gsrc));
            CP_ASYNC16(s0 + ALO + doff, (const void*)(g_a_lo + gsrc));
            CP_ASYNC16(s0 + BOF + doff, (const void*)(g_wt + gsrcB));
        }
    };

    // prologue: stages 0 and 1
    load_stage(0, 0);
    CP_COMMIT();
    load_stage(1, BK);
    CP_COMMIT();

    const int NKC = DDIM / BK;   // 32
    for (int kc = 0; kc < NKC; kc++) {
        CP_WAIT1();
        __syncthreads();

        // issue loads for kc+2 into the stage freed last iteration
        if (kc + 2 < NKC) load_stage((kc + 2) % STAGES, (kc + 2) * BK);
        CP_COMMIT();

        const uint32_t s0 = sb + (kc % STAGES) * STAGE_B;

        #pragma unroll
        for (int ks = 0; ks < 2; ks++) {
            uint32_t ah[2][4], al[2][4], bh[16];
            // A fragments (2 m-tiles), hi and lo
            #pragma unroll
            for (int mt = 0; mt < 2; mt++) {
                int m = warp_m * 32 + mt * 16 + a_mlane;
                uint32_t off = (uint32_t)(m * 64 + (((ks * 2 + a_kh) ^ (m & 3)) << 4));
                LDSM_X4(ah[mt][0], ah[mt][1], ah[mt][2], ah[mt][3], s0 + AHI + off);
                LDSM_X4(al[mt][0], al[mt][1], al[mt][2], al[mt][3], s0 + ALO + off);
            }
            // B fragments (4 n-tile pairs -> 8 n-tiles)
            #pragma unroll
            for (int np = 0; np < 4; np++) {
                int n = warp_n * 64 + np * 16 + b_nlane;
                uint32_t off = (uint32_t)(n * 64 + (((ks * 2 + b_kh) ^ (n & 3)) << 4));
                LDSM_X4(bh[np * 4 + 0], bh[np * 4 + 1], bh[np * 4 + 2], bh[np * 4 + 3],
                        s0 + BOF + off);
            }
            // 2 passes: a_hi*b + a_lo*b
            #pragma unroll
            for (int mt = 0; mt < 2; mt++) {
                #pragma unroll
                for (int nt = 0; nt < 8; nt++) {
                    int bi = (nt >> 1) * 4 + (nt & 1) * 2;
                    MMA_16816(acc[mt][nt], ah[mt][0], ah[mt][1], ah[mt][2], ah[mt][3],
                              bh[bi], bh[bi + 1]);
                    MMA_16816(acc[mt][nt], al[mt][0], al[mt][1], al[mt][2], al[mt][3],
                              bh[bi], bh[bi + 1]);
                }
            }
        }
    }

    // ---- epilogue: bias + leaky + Wc contraction, quad reduce, atomicAdd ----
    float part[2][2][4];
    #pragma unroll
    for (int mt = 0; mt < 2; mt++)
        #pragma unroll
        for (int h = 0; h < 2; h++)
            #pragma unroll
            for (int s = 0; s < 4; s++) part[mt][h][s] = 0.0f;

    #pragma unroll
    for (int nt = 0; nt < 8; nt++) {
        #pragma unroll
        for (int e = 0; e < 4; e++) {
            int n = n0 + warp_n * 64 + nt * 8 + (lane & 3) * 2 + (e & 1);
            if (n >= NTOT) continue;
            float bias = (n < MLPD) ? __ldg(bdep + n) : __ldg(bhead + n - MLPD);
            float w0 = __ldg(Wc + 2 * n);
            float w1 = __ldg(Wc + 2 * n + 1);
            int s = (n < MLPD) ? 0 : 2;
            int half = e >> 1;
            #pragma unroll
            for (int mt = 0; mt < 2; mt++) {
                float v = acc[mt][nt][e] + bias;
                v = (v > 0.0f) ? v : NEG_SLOPE * v;
                part[mt][half][s + 0] += v * w0;
                part[mt][half][s + 1] += v * w1;
            }
        }
    }

    // reduce across the 4 lanes of each quad (they share the same rows)
    #pragma unroll
    for (int mt = 0; mt < 2; mt++)
        #pragma unroll
        for (int h = 0; h < 2; h++)
            #pragma unroll
            for (int s = 0; s < 4; s++) {
                float v = part[mt][h][s];
                v += __shfl_xor_sync(0xffffffffu, v, 1);
                v += __shfl_xor_sync(0xffffffffu, v, 2);
                part[mt][h][s] = v;
            }

    if ((lane & 3) == 0) {
        #pragma unroll
        for (int mt = 0; mt < 2; mt++)
            #pragma unroll
            for (int h = 0; h < 2; h++) {
                int row = row0 + warp_m * 32 + mt * 16 + (lane >> 2) + h * 8;
                #pragma unroll
                for (int s = 0; s < 4; s++)
                    atomicAdd(&g_scores[row * 4 + s], part[mt][h][s]);
            }
    }
}

// ---------------------------------------------------------------------------
// Kernel 4: broadcast pairwise add -> out[b,i,j,c]
// ---------------------------------------------------------------------------
__global__ __launch_bounds__(256)
void broadcast_add_kernel(const float* __restrict__ bc, float* __restrict__ out) {
    __shared__ float hs[SEQ * 2];
    const int row = blockIdx.x;
    const int b   = row >> 10;
    const int tid = threadIdx.x;

    for (int j = tid; j < SEQ; j += 256) {
        int hr = (b << 10) + j;
        hs[2 * j + 0] = g_scores[hr * 4 + 2];
        hs[2 * j + 1] = g_scores[hr * 4 + 3];
    }
    __syncthreads();

    const float d0 = g_scores[row * 4 + 0] + bc[0];
    const float d1 = g_scores[row * 4 + 1] + bc[1];

    float4* o = reinterpret_cast<float4*>(out + (size_t)row * (SEQ * 2));
    for (int f = tid; f < SEQ * 2 / 4; f += 256) {
        int j = 2 * f;
        float4 v;
        v.x = d0 + hs[2 * j + 0];
        v.y = d1 + hs[2 * j + 1];
        v.z = d0 + hs[2 * j + 2];
        v.w = d1 + hs[2 * j + 3];
        o[f] = v;
    }
}

// ---------------------------------------------------------------------------
// Launch
// ---------------------------------------------------------------------------
extern "C" void kernel_launch(void* const* d_in, const int* in_sizes, int n_in,
                              void* d_out, int out_size)
{
    (void)in_sizes; (void)n_in; (void)out_size;
    const float* hidden = (const float*)d_in[0];
    const float* Wd     = (const float*)d_in[1];
    const float* bd     = (const float*)d_in[2];
    const float* Wh     = (const float*)d_in[3];
    const float* bh     = (const float*)d_in[4];
    const float* Wc     = (const float*)d_in[5];
    const float* bc     = (const float*)d_in[6];
    float* out          = (float*)d_out;

    cudaFuncSetAttribute(gemm_mma_kernel,
                         cudaFuncAttributeMaxDynamicSharedMemorySize, DYN_SMEM);

    zero_scores_kernel<<<(ROWS * 4 + 255) / 256, 256>>>();
    convert_a_kernel<<<ROWS * DDIM / 4 / 256, 256>>>(hidden);
    transpose_w_kernel<<<dim3(NPAD / 32, DDIM / 32), dim3(32, 8)>>>(Wd, Wh);
    gemm_mma_kernel<<<dim3(NPAD / BN, ROWS / BM), 256, DYN_SMEM>>>(bd, bh, Wc);
    broadcast_add_kernel<<<ROWS, 256>>>(bc, out);
}